// round 11
// baseline (speedup 1.0000x reference)
#include <cuda_runtime.h>
#include <cuda_fp16.h>
#include <cstdint>

// ---------------------------------------------------------------------------
// DeepSet (legacy-MMA path):
//   phi:  relu(X@W1+b1)@W2+b2 via mma.sync.m16n8k16 with FP16 ACCUMULATE
//         (2 chained k16 MMAs per fp16 C chunk, promoted to fp32 per k32)
//   summ: sorted-run segmented reduction, per-run atomics into g_summ
//   rho:  scalar fp32 kernel
// ---------------------------------------------------------------------------

#define MAX_AGENTS 50000
__device__ float g_summ[MAX_AGENTS * 64];

// ---- helpers --------------------------------------------------------------
__device__ __forceinline__ unsigned packh2(float a, float b) {
    __half2 h = __floats2half2_rn(a, b);
    return *reinterpret_cast<unsigned*>(&h);
}

// fp16-accumulate MMA: D(f16x2 x2) = A*B + C(f16x2 x2)
__device__ __forceinline__ void mma_f16acc(unsigned& d0, unsigned& d1,
                                           unsigned a0, unsigned a1, unsigned a2, unsigned a3,
                                           unsigned b0, unsigned b1) {
    asm volatile(
        "mma.sync.aligned.m16n8k16.row.col.f16.f16.f16.f16 "
        "{%0,%1}, {%2,%3,%4,%5}, {%6,%7}, {%0,%1};"
        : "+r"(d0), "+r"(d1)
        : "r"(a0), "r"(a1), "r"(a2), "r"(a3), "r"(b0), "r"(b1));
}

// ---- shared layout (bytes) ------------------------------------------------
static constexpr int ST_ROWS  = 256;
static constexpr int XSTRIDE  = 72;                    // halves
static constexpr int OFF_X    = 0;                     // 36864 B
static constexpr int OFF_W1   = ST_ROWS * XSTRIDE * 2; // 36864
static constexpr int OFF_W2   = OFF_W1 + 8192;         // 45056
static constexpr int OFF_B1   = OFF_W2 + 8192;         // 53248
static constexpr int OFF_B2   = OFF_B1 + 256;          // 53504
static constexpr int OFF_SEG  = OFF_B2 + 256;          // 53760
static constexpr int SMEM_TOTAL = OFF_SEG + ST_ROWS * 4; // 54784

// ---- zero scratch ---------------------------------------------------------
__global__ void DeepSet_zero_kernel(int n) {
    for (int i = blockIdx.x * blockDim.x + threadIdx.x; i < n; i += gridDim.x * blockDim.x)
        g_summ[i] = 0.0f;
}

// ---- fused phi + segment-sum ----------------------------------------------
__global__ __launch_bounds__(256, 2)
void DeepSet_phi_kernel(const float* __restrict__ nb,
                        const float* __restrict__ w1, const float* __restrict__ b1,
                        const float* __restrict__ w2, const float* __restrict__ b2,
                        const int* __restrict__ seg,
                        int nNb, int nSuper) {
    extern __shared__ unsigned char smem[];
    __half*   sX  = reinterpret_cast<__half*>(smem + OFF_X);
    uint2*    bf1 = reinterpret_cast<uint2*>(smem + OFF_W1);
    uint2*    bf2 = reinterpret_cast<uint2*>(smem + OFF_W2);
    float*    sB1 = reinterpret_cast<float*>(smem + OFF_B1);
    float*    sB2 = reinterpret_cast<float*>(smem + OFF_B2);
    int*      sSeg = reinterpret_cast<int*>(smem + OFF_SEG);

    const int tid  = threadIdx.x;
    const int lane = tid & 31;
    const int wrp  = tid >> 5;          // 8 warps, each owns 32 rows
    const int g    = lane >> 2;
    const int t    = lane & 3;

    // --- stage W1/W2 as pre-swizzled m16n8k16 B fragments ------------------
    for (int i = tid; i < 1024; i += 256) {
        const int ln = i & 31, n = (i >> 5) & 7, kk = i >> 8;
        const int gg = ln >> 2, tt = ln & 3;
        const int rw = kk * 16 + 2 * tt;
        const int cl = n * 8 + gg;
        uint2 u1, u2;
        u1.x = packh2(w1[rw * 64 + cl],       w1[(rw + 1) * 64 + cl]);
        u1.y = packh2(w1[(rw + 8) * 64 + cl], w1[(rw + 9) * 64 + cl]);
        u2.x = packh2(w2[rw * 64 + cl],       w2[(rw + 1) * 64 + cl]);
        u2.y = packh2(w2[(rw + 8) * 64 + cl], w2[(rw + 9) * 64 + cl]);
        bf1[i] = u1;
        bf2[i] = u2;
    }
    if (tid < 64) { sB1[tid] = b1[tid]; sB2[tid] = b2[tid]; }
    __syncthreads();

    const unsigned* sXu = reinterpret_cast<const unsigned*>(sX);

    for (int sp = blockIdx.x; sp < nSuper; sp += gridDim.x) {
        const long base = (long)sp * ST_ROWS;

        // ---- fill X (fp16): 8 floats -> uint4 per iter ----
        for (int i = tid; i < ST_ROWS * 8; i += 256) {
            const int r  = i >> 3;
            const int c8 = (i & 7) << 3;
            const long gr = base + r;
            uint4 o;
            if (gr < nNb) {
                const float4 va = *reinterpret_cast<const float4*>(nb + gr * 64 + c8);
                const float4 vb = *reinterpret_cast<const float4*>(nb + gr * 64 + c8 + 4);
                o.x = packh2(va.x, va.y); o.y = packh2(va.z, va.w);
                o.z = packh2(vb.x, vb.y); o.w = packh2(vb.z, vb.w);
            } else {
                o.x = o.y = o.z = o.w = 0u;
            }
            *reinterpret_cast<uint4*>(&sX[r * XSTRIDE + c8]) = o;
        }
        {
            const long gr = base + tid;   // blockDim == ST_ROWS
            sSeg[tid] = (gr < nNb) ? seg[gr] : -1;
        }
        __syncthreads();

        const int rowBase = wrp * 32;
        float acc[2][8][4];

        // =============== layer 1: H = relu(X@W1 + b1) ===============
        #pragma unroll
        for (int m = 0; m < 2; ++m)
            #pragma unroll
            for (int n = 0; n < 8; ++n)
                #pragma unroll
                for (int q = 0; q < 4; ++q) acc[m][n][q] = 0.0f;

        #pragma unroll
        for (int kp = 0; kp < 2; ++kp) {         // k32 chunk, fp16 C inside
            unsigned c[2][8][2];
            #pragma unroll
            for (int m = 0; m < 2; ++m)
                #pragma unroll
                for (int n = 0; n < 8; ++n) { c[m][n][0] = 0u; c[m][n][1] = 0u; }

            #pragma unroll
            for (int kh = 0; kh < 2; ++kh) {
                const int kk = kp * 2 + kh;
                const int cA = kk * 16 + 2 * t;
                unsigned a[2][4];
                #pragma unroll
                for (int m = 0; m < 2; ++m) {
                    const int rb = rowBase + m * 16;
                    a[m][0] = sXu[((rb + g)     * XSTRIDE + cA)     >> 1];
                    a[m][1] = sXu[((rb + g + 8) * XSTRIDE + cA)     >> 1];
                    a[m][2] = sXu[((rb + g)     * XSTRIDE + cA + 8) >> 1];
                    a[m][3] = sXu[((rb + g + 8) * XSTRIDE + cA + 8) >> 1];
                }
                #pragma unroll
                for (int n = 0; n < 8; ++n) {
                    const uint2 b = bf1[(kk * 8 + n) * 32 + lane];
                    mma_f16acc(c[0][n][0], c[0][n][1],
                               a[0][0], a[0][1], a[0][2], a[0][3], b.x, b.y);
                    mma_f16acc(c[1][n][0], c[1][n][1],
                               a[1][0], a[1][1], a[1][2], a[1][3], b.x, b.y);
                }
            }
            // promote fp16 chunk -> fp32 accumulators
            #pragma unroll
            for (int m = 0; m < 2; ++m)
                #pragma unroll
                for (int n = 0; n < 8; ++n) {
                    const float2 f0 = __half22float2(*reinterpret_cast<__half2*>(&c[m][n][0]));
                    const float2 f1 = __half22float2(*reinterpret_cast<__half2*>(&c[m][n][1]));
                    acc[m][n][0] += f0.x; acc[m][n][1] += f0.y;
                    acc[m][n][2] += f1.x; acc[m][n][3] += f1.y;
                }
        }
        // epilogue 1: bias + relu -> fp16 H back into sX (own rows only)
        #pragma unroll
        for (int m = 0; m < 2; ++m) {
            const int rb = rowBase + m * 16;
            #pragma unroll
            for (int n = 0; n < 8; ++n) {
                const int col = n * 8 + 2 * t;
                const float bb0 = sB1[col], bb1 = sB1[col + 1];
                const unsigned h0 = packh2(fmaxf(acc[m][n][0] + bb0, 0.0f),
                                           fmaxf(acc[m][n][1] + bb1, 0.0f));
                const unsigned h1 = packh2(fmaxf(acc[m][n][2] + bb0, 0.0f),
                                           fmaxf(acc[m][n][3] + bb1, 0.0f));
                *reinterpret_cast<unsigned*>(&sX[(rb + g)     * XSTRIDE + col]) = h0;
                *reinterpret_cast<unsigned*>(&sX[(rb + g + 8) * XSTRIDE + col]) = h1;
            }
        }
        __syncwarp();

        // =============== layer 2: Y = H@W2 + b2 ===============
        #pragma unroll
        for (int m = 0; m < 2; ++m)
            #pragma unroll
            for (int n = 0; n < 8; ++n)
                #pragma unroll
                for (int q = 0; q < 4; ++q) acc[m][n][q] = 0.0f;

        #pragma unroll
        for (int kp = 0; kp < 2; ++kp) {
            unsigned c[2][8][2];
            #pragma unroll
            for (int m = 0; m < 2; ++m)
                #pragma unroll
                for (int n = 0; n < 8; ++n) { c[m][n][0] = 0u; c[m][n][1] = 0u; }

            #pragma unroll
            for (int kh = 0; kh < 2; ++kh) {
                const int kk = kp * 2 + kh;
                const int cA = kk * 16 + 2 * t;
                unsigned a[2][4];
                #pragma unroll
                for (int m = 0; m < 2; ++m) {
                    const int rb = rowBase + m * 16;
                    a[m][0] = sXu[((rb + g)     * XSTRIDE + cA)     >> 1];
                    a[m][1] = sXu[((rb + g + 8) * XSTRIDE + cA)     >> 1];
                    a[m][2] = sXu[((rb + g)     * XSTRIDE + cA + 8) >> 1];
                    a[m][3] = sXu[((rb + g + 8) * XSTRIDE + cA + 8) >> 1];
                }
                #pragma unroll
                for (int n = 0; n < 8; ++n) {
                    const uint2 b = bf2[(kk * 8 + n) * 32 + lane];
                    mma_f16acc(c[0][n][0], c[0][n][1],
                               a[0][0], a[0][1], a[0][2], a[0][3], b.x, b.y);
                    mma_f16acc(c[1][n][0], c[1][n][1],
                               a[1][0], a[1][1], a[1][2], a[1][3], b.x, b.y);
                }
            }
            #pragma unroll
            for (int m = 0; m < 2; ++m)
                #pragma unroll
                for (int n = 0; n < 8; ++n) {
                    const float2 f0 = __half22float2(*reinterpret_cast<__half2*>(&c[m][n][0]));
                    const float2 f1 = __half22float2(*reinterpret_cast<__half2*>(&c[m][n][1]));
                    acc[m][n][0] += f0.x; acc[m][n][1] += f0.y;
                    acc[m][n][2] += f1.x; acc[m][n][3] += f1.y;
                }
        }
        // epilogue 2: bias -> fp16 Y into sX (own rows only)
        #pragma unroll
        for (int m = 0; m < 2; ++m) {
            const int rb = rowBase + m * 16;
            #pragma unroll
            for (int n = 0; n < 8; ++n) {
                const int col = n * 8 + 2 * t;
                const float bb0 = sB2[col], bb1 = sB2[col + 1];
                const unsigned y0 = packh2(acc[m][n][0] + bb0, acc[m][n][1] + bb1);
                const unsigned y1 = packh2(acc[m][n][2] + bb0, acc[m][n][3] + bb1);
                *reinterpret_cast<unsigned*>(&sX[(rb + g)     * XSTRIDE + col]) = y0;
                *reinterpret_cast<unsigned*>(&sX[(rb + g + 8) * XSTRIDE + col]) = y1;
            }
        }
        __syncthreads();

        // ---- sorted-run segmented reduction: 4 chunks x 64 rows, 64 cols ----
        {
            const int colc  = tid & 63;
            const int rbeg  = (tid >> 6) * 64;
            float racc = 0.0f;
            int   cur  = -1;
            #pragma unroll 4
            for (int r = rbeg; r < rbeg + 64; ++r) {
                const int s = sSeg[r];
                if (s != cur) {
                    if (cur >= 0) atomicAdd(&g_summ[cur * 64 + colc], racc);
                    cur = s;
                    racc = 0.0f;
                }
                if (s >= 0) racc += __half2float(sX[r * XSTRIDE + colc]);
            }
            if (cur >= 0) atomicAdd(&g_summ[cur * 64 + colc], racc);
        }
        __syncthreads();
    }
}

// ---- rho MLP: scalar fp32, 64 agents per block -----------------------------
__global__ __launch_bounds__(256)
void DeepSet_rho_kernel(const float* __restrict__ rw1, const float* __restrict__ rb1,
                        const float* __restrict__ rw2, const float* __restrict__ rb2,
                        float* __restrict__ out, int nAgents) {
    __shared__ float sW[64 * 64];
    __shared__ float sW2[64 * 2];
    __shared__ float sB1r[64];
    __shared__ float sB2r[2];

    const int tid  = threadIdx.x;
    const int lane = tid & 31;
    const int wrp  = tid >> 5;

    for (int i = tid; i < 64 * 64; i += 256) sW[i] = rw1[i];
    for (int i = tid; i < 128; i += 256) sW2[i] = rw2[i];
    if (tid < 64) sB1r[tid] = rb1[tid];
    if (tid < 2)  sB2r[tid] = rb2[tid];
    __syncthreads();

    #pragma unroll 1
    for (int a = 0; a < 8; ++a) {
        const int row = blockIdx.x * 64 + wrp * 8 + a;
        if (row >= nAgents) continue;

        const float x0 = g_summ[row * 64 + lane];
        const float x1 = g_summ[row * 64 + lane + 32];

        float r0 = sB1r[lane];
        float r1 = sB1r[lane + 32];
        #pragma unroll
        for (int k = 0; k < 32; ++k) {
            const float xk = __shfl_sync(0xFFFFFFFFu, x0, k);
            r0 = fmaf(xk, sW[k * 64 + lane],      r0);
            r1 = fmaf(xk, sW[k * 64 + lane + 32], r1);
        }
        #pragma unroll
        for (int k = 0; k < 32; ++k) {
            const float xk = __shfl_sync(0xFFFFFFFFu, x1, k);
            r0 = fmaf(xk, sW[(k + 32) * 64 + lane],      r0);
            r1 = fmaf(xk, sW[(k + 32) * 64 + lane + 32], r1);
        }
        r0 = fmaxf(r0, 0.0f);
        r1 = fmaxf(r1, 0.0f);

        float p0 = r0 * sW2[lane * 2 + 0] + r1 * sW2[(lane + 32) * 2 + 0];
        float p1 = r0 * sW2[lane * 2 + 1] + r1 * sW2[(lane + 32) * 2 + 1];
        #pragma unroll
        for (int off = 16; off > 0; off >>= 1) {
            p0 += __shfl_xor_sync(0xFFFFFFFFu, p0, off);
            p1 += __shfl_xor_sync(0xFFFFFFFFu, p1, off);
        }
        if (lane == 0) {
            out[row * 2 + 0] = p0 + sB2r[0];
            out[row * 2 + 1] = p1 + sB2r[1];
        }
    }
}

// ---- launch ----------------------------------------------------------------
extern "C" void kernel_launch(void* const* d_in, const int* in_sizes, int n_in,
                              void* d_out, int out_size) {
    const float* neighbors = (const float*)d_in[0];
    const float* phi_w1    = (const float*)d_in[1];
    const float* phi_b1    = (const float*)d_in[2];
    const float* phi_w2    = (const float*)d_in[3];
    const float* phi_b2    = (const float*)d_in[4];
    const float* rho_w1    = (const float*)d_in[5];
    const float* rho_b1    = (const float*)d_in[6];
    const float* rho_w2    = (const float*)d_in[7];
    const float* rho_b2    = (const float*)d_in[8];
    const int*   seg       = (const int*)d_in[9];
    float* out = (float*)d_out;

    const int nNb     = in_sizes[0] / 64;
    const int nAgents = out_size / 2;
    const int nSuper  = (nNb + ST_ROWS - 1) / ST_ROWS;

    cudaFuncSetAttribute(DeepSet_phi_kernel,
                         cudaFuncAttributeMaxDynamicSharedMemorySize, SMEM_TOTAL);

    DeepSet_zero_kernel<<<512, 256>>>(nAgents * 64);

    int grid = 296;  // 148 SMs x 2 CTAs
    if (grid > nSuper) grid = nSuper;
    DeepSet_phi_kernel<<<grid, 256, SMEM_TOTAL>>>(
        neighbors, phi_w1, phi_b1, phi_w2, phi_b2, seg, nNb, nSuper);

    DeepSet_rho_kernel<<<(nAgents + 63) / 64, 256>>>(rho_w1, rho_b1, rho_w2, rho_b2,
                                                     out, nAgents);
}

// round 16
// speedup vs baseline: 1.1054x; 1.1054x over previous
#include <cuda_runtime.h>
#include <cuda_fp16.h>
#include <cstdint>

// ---------------------------------------------------------------------------
// DeepSet (legacy-MMA path; HMMA rt=32cyc/SMSP is the hard floor):
//   phi:  relu(X@W1+b1)@W2+b2 via mma.sync.m16n8k16.f16 (fp32 accum)
//   summ: sorted-run segmented reduction, per-run atomics into g_summ
//   rho:  scalar fp32 kernel
// Each CTA = 2 independent 128-row streams (named barriers) -> 4 phase
// streams per SM, keeping the tensor pipe busy during fill/reduce phases.
// (Resubmission of the R12 design: R14 bench was an infra failure, no data.)
// ---------------------------------------------------------------------------

#define MAX_AGENTS 50000
__device__ float g_summ[MAX_AGENTS * 64];

// ---- helpers --------------------------------------------------------------
__device__ __forceinline__ unsigned packh2(float a, float b) {
    __half2 h = __floats2half2_rn(a, b);
    return *reinterpret_cast<unsigned*>(&h);
}

__device__ __forceinline__ void mma_fp16(float& c0, float& c1, float& c2, float& c3,
                                         unsigned a0, unsigned a1, unsigned a2, unsigned a3,
                                         unsigned b0, unsigned b1) {
    asm volatile(
        "mma.sync.aligned.m16n8k16.row.col.f32.f16.f16.f32 "
        "{%0,%1,%2,%3}, {%4,%5,%6,%7}, {%8,%9}, {%0,%1,%2,%3};"
        : "+f"(c0), "+f"(c1), "+f"(c2), "+f"(c3)
        : "r"(a0), "r"(a1), "r"(a2), "r"(a3), "r"(b0), "r"(b1));
}

#define BARH(id) asm volatile("bar.sync %0, 128;" :: "r"(id) : "memory")

// ---- shared layout (bytes) ------------------------------------------------
// Two independent 128-row halves. Half stride 18432B = 144 banks*rows, so the
// XSTRIDE=72 (halves) bank pattern (row*36 % 32 == 4) is preserved per half.
static constexpr int H_ROWS   = 128;                   // rows per stream
static constexpr int XSTRIDE  = 72;                    // halves
static constexpr int XH_BYTES = H_ROWS * XSTRIDE * 2;  // 18432
static constexpr int OFF_X0   = 0;
static constexpr int OFF_X1   = XH_BYTES;              // 18432
static constexpr int OFF_W1   = 2 * XH_BYTES;          // 36864
static constexpr int OFF_W2   = OFF_W1 + 8192;         // 45056
static constexpr int OFF_B1   = OFF_W2 + 8192;         // 53248
static constexpr int OFF_B2   = OFF_B1 + 256;          // 53504
static constexpr int OFF_SEG0 = OFF_B2 + 256;          // 53760
static constexpr int OFF_SEG1 = OFF_SEG0 + 512;        // 54272
static constexpr int SMEM_TOTAL = OFF_SEG1 + 512;      // 54784

// ---- zero scratch ---------------------------------------------------------
__global__ void DeepSet_zero_kernel(int n) {
    for (int i = blockIdx.x * blockDim.x + threadIdx.x; i < n; i += gridDim.x * blockDim.x)
        g_summ[i] = 0.0f;
}

// ---- fused phi + segment-sum ----------------------------------------------
__global__ __launch_bounds__(256, 2)
void DeepSet_phi_kernel(const float* __restrict__ nb,
                        const float* __restrict__ w1, const float* __restrict__ b1,
                        const float* __restrict__ w2, const float* __restrict__ b2,
                        const int* __restrict__ seg,
                        int nNb, int nTiles) {
    extern __shared__ unsigned char smem[];
    uint2*  bf1 = reinterpret_cast<uint2*>(smem + OFF_W1);
    uint2*  bf2 = reinterpret_cast<uint2*>(smem + OFF_W2);
    float*  sB1 = reinterpret_cast<float*>(smem + OFF_B1);
    float*  sB2 = reinterpret_cast<float*>(smem + OFF_B2);

    const int tid  = threadIdx.x;
    const int half = tid >> 7;          // stream 0 / 1
    const int wt   = tid & 127;         // id within stream (4 warps)
    const int lane = tid & 31;
    const int wrp  = wt >> 5;           // 0..3: each warp owns 32 rows
    const int g    = lane >> 2;
    const int t    = lane & 3;
    const int bid  = half + 1;          // named barrier per stream

    // --- stage W1/W2 as pre-swizzled m16n8k16 B fragments (whole CTA) ------
    for (int i = tid; i < 1024; i += 256) {
        const int ln = i & 31, n = (i >> 5) & 7, kk = i >> 8;
        const int gg = ln >> 2, tt = ln & 3;
        const int rw = kk * 16 + 2 * tt;
        const int cl = n * 8 + gg;
        uint2 u1, u2;
        u1.x = packh2(w1[rw * 64 + cl],       w1[(rw + 1) * 64 + cl]);
        u1.y = packh2(w1[(rw + 8) * 64 + cl], w1[(rw + 9) * 64 + cl]);
        u2.x = packh2(w2[rw * 64 + cl],       w2[(rw + 1) * 64 + cl]);
        u2.y = packh2(w2[(rw + 8) * 64 + cl], w2[(rw + 9) * 64 + cl]);
        bf1[i] = u1;
        bf2[i] = u2;
    }
    if (tid < 64) { sB1[tid] = b1[tid]; sB2[tid] = b2[tid]; }
    __syncthreads();

    // per-stream resources
    __half*         sX   = reinterpret_cast<__half*>(smem + (half ? OFF_X1 : OFF_X0));
    const unsigned* sXu  = reinterpret_cast<const unsigned*>(sX);
    int*            sSeg = reinterpret_cast<int*>(smem + (half ? OFF_SEG1 : OFF_SEG0));
    const int stride = gridDim.x * 2;

    for (int tile = blockIdx.x * 2 + half; tile < nTiles; tile += stride) {
        const long base = (long)tile * H_ROWS;

        // ---- fill X (fp16): 8 floats -> uint4 per iter; 8 iters/thread ----
        for (int i = wt; i < H_ROWS * 8; i += 128) {
            const int r  = i >> 3;
            const int c8 = (i & 7) << 3;
            const long gr = base + r;
            uint4 o;
            if (gr < nNb) {
                const float4 va = *reinterpret_cast<const float4*>(nb + gr * 64 + c8);
                const float4 vb = *reinterpret_cast<const float4*>(nb + gr * 64 + c8 + 4);
                o.x = packh2(va.x, va.y); o.y = packh2(va.z, va.w);
                o.z = packh2(vb.x, vb.y); o.w = packh2(vb.z, vb.w);
            } else {
                o.x = o.y = o.z = o.w = 0u;
            }
            *reinterpret_cast<uint4*>(&sX[r * XSTRIDE + c8]) = o;
        }
        {
            const long gr = base + wt;   // 128 ids per stream
            sSeg[wt] = (gr < nNb) ? seg[gr] : -1;
        }
        BARH(bid);

        const int rowBase = wrp * 32;
        float acc[2][8][4];

        // =============== layer 1: H = relu(X@W1 + b1) ===============
        #pragma unroll
        for (int m = 0; m < 2; ++m)
            #pragma unroll
            for (int n = 0; n < 8; ++n)
                #pragma unroll
                for (int q = 0; q < 4; ++q) acc[m][n][q] = 0.0f;

        #pragma unroll
        for (int kk = 0; kk < 4; ++kk) {
            const int cA = kk * 16 + 2 * t;
            unsigned a[2][4];
            #pragma unroll
            for (int m = 0; m < 2; ++m) {
                const int rb = rowBase + m * 16;
                a[m][0] = sXu[((rb + g)     * XSTRIDE + cA)     >> 1];
                a[m][1] = sXu[((rb + g + 8) * XSTRIDE + cA)     >> 1];
                a[m][2] = sXu[((rb + g)     * XSTRIDE + cA + 8) >> 1];
                a[m][3] = sXu[((rb + g + 8) * XSTRIDE + cA + 8) >> 1];
            }
            #pragma unroll
            for (int n = 0; n < 8; ++n) {
                const uint2 b = bf1[(kk * 8 + n) * 32 + lane];
                mma_fp16(acc[0][n][0], acc[0][n][1], acc[0][n][2], acc[0][n][3],
                         a[0][0], a[0][1], a[0][2], a[0][3], b.x, b.y);
                mma_fp16(acc[1][n][0], acc[1][n][1], acc[1][n][2], acc[1][n][3],
                         a[1][0], a[1][1], a[1][2], a[1][3], b.x, b.y);
            }
        }
        // epilogue 1: bias + relu -> fp16 H back into sX (own rows only)
        #pragma unroll
        for (int m = 0; m < 2; ++m) {
            const int rb = rowBase + m * 16;
            #pragma unroll
            for (int n = 0; n < 8; ++n) {
                const int col = n * 8 + 2 * t;
                const float bb0 = sB1[col], bb1 = sB1[col + 1];
                const unsigned h0 = packh2(fmaxf(acc[m][n][0] + bb0, 0.0f),
                                           fmaxf(acc[m][n][1] + bb1, 0.0f));
                const unsigned h1 = packh2(fmaxf(acc[m][n][2] + bb0, 0.0f),
                                           fmaxf(acc[m][n][3] + bb1, 0.0f));
                *reinterpret_cast<unsigned*>(&sX[(rb + g)     * XSTRIDE + col]) = h0;
                *reinterpret_cast<unsigned*>(&sX[(rb + g + 8) * XSTRIDE + col]) = h1;
            }
        }
        __syncwarp();

        // =============== layer 2: Y = H@W2 + b2 ===============
        #pragma unroll
        for (int m = 0; m < 2; ++m)
            #pragma unroll
            for (int n = 0; n < 8; ++n)
                #pragma unroll
                for (int q = 0; q < 4; ++q) acc[m][n][q] = 0.0f;

        #pragma unroll
        for (int kk = 0; kk < 4; ++kk) {
            const int cA = kk * 16 + 2 * t;
            unsigned a[2][4];
            #pragma unroll
            for (int m = 0; m < 2; ++m) {
                const int rb = rowBase + m * 16;
                a[m][0] = sXu[((rb + g)     * XSTRIDE + cA)     >> 1];
                a[m][1] = sXu[((rb + g + 8) * XSTRIDE + cA)     >> 1];
                a[m][2] = sXu[((rb + g)     * XSTRIDE + cA + 8) >> 1];
                a[m][3] = sXu[((rb + g + 8) * XSTRIDE + cA + 8) >> 1];
            }
            #pragma unroll
            for (int n = 0; n < 8; ++n) {
                const uint2 b = bf2[(kk * 8 + n) * 32 + lane];
                mma_fp16(acc[0][n][0], acc[0][n][1], acc[0][n][2], acc[0][n][3],
                         a[0][0], a[0][1], a[0][2], a[0][3], b.x, b.y);
                mma_fp16(acc[1][n][0], acc[1][n][1], acc[1][n][2], acc[1][n][3],
                         a[1][0], a[1][1], a[1][2], a[1][3], b.x, b.y);
            }
        }
        // epilogue 2: bias -> fp16 Y into sX (own rows only)
        #pragma unroll
        for (int m = 0; m < 2; ++m) {
            const int rb = rowBase + m * 16;
            #pragma unroll
            for (int n = 0; n < 8; ++n) {
                const int col = n * 8 + 2 * t;
                const float bb0 = sB2[col], bb1 = sB2[col + 1];
                const unsigned y0 = packh2(acc[m][n][0] + bb0, acc[m][n][1] + bb1);
                const unsigned y1 = packh2(acc[m][n][2] + bb0, acc[m][n][3] + bb1);
                *reinterpret_cast<unsigned*>(&sX[(rb + g)     * XSTRIDE + col]) = y0;
                *reinterpret_cast<unsigned*>(&sX[(rb + g + 8) * XSTRIDE + col]) = y1;
            }
        }
        BARH(bid);

        // ---- sorted-run segmented reduction: 2 chunks x 64 rows, 64 cols ----
        {
            const int colc = wt & 63;
            const int rbeg = (wt >> 6) * 64;
            float racc = 0.0f;
            int   cur  = -1;
            #pragma unroll 4
            for (int r = rbeg; r < rbeg + 64; ++r) {
                const int s = sSeg[r];
                if (s != cur) {
                    if (cur >= 0) atomicAdd(&g_summ[cur * 64 + colc], racc);
                    cur = s;
                    racc = 0.0f;
                }
                if (s >= 0) racc += __half2float(sX[r * XSTRIDE + colc]);
            }
            if (cur >= 0) atomicAdd(&g_summ[cur * 64 + colc], racc);
        }
        BARH(bid);   // protect X/seg reuse next iteration
    }
}

// ---- rho MLP: scalar fp32, 64 agents per block -----------------------------
__global__ __launch_bounds__(256)
void DeepSet_rho_kernel(const float* __restrict__ rw1, const float* __restrict__ rb1,
                        const float* __restrict__ rw2, const float* __restrict__ rb2,
                        float* __restrict__ out, int nAgents) {
    __shared__ float sW[64 * 64];
    __shared__ float sW2[64 * 2];
    __shared__ float sB1r[64];
    __shared__ float sB2r[2];

    const int tid  = threadIdx.x;
    const int lane = tid & 31;
    const int wrp  = tid >> 5;

    for (int i = tid; i < 64 * 64; i += 256) sW[i] = rw1[i];
    for (int i = tid; i < 128; i += 256) sW2[i] = rw2[i];
    if (tid < 64) sB1r[tid] = rb1[tid];
    if (tid < 2)  sB2r[tid] = rb2[tid];
    __syncthreads();

    #pragma unroll 1
    for (int a = 0; a < 8; ++a) {
        const int row = blockIdx.x * 64 + wrp * 8 + a;
        if (row >= nAgents) continue;

        const float x0 = g_summ[row * 64 + lane];
        const float x1 = g_summ[row * 64 + lane + 32];

        float r0 = sB1r[lane];
        float r1 = sB1r[lane + 32];
        #pragma unroll
        for (int k = 0; k < 32; ++k) {
            const float xk = __shfl_sync(0xFFFFFFFFu, x0, k);
            r0 = fmaf(xk, sW[k * 64 + lane],      r0);
            r1 = fmaf(xk, sW[k * 64 + lane + 32], r1);
        }
        #pragma unroll
        for (int k = 0; k < 32; ++k) {
            const float xk = __shfl_sync(0xFFFFFFFFu, x1, k);
            r0 = fmaf(xk, sW[(k + 32) * 64 + lane],      r0);
            r1 = fmaf(xk, sW[(k + 32) * 64 + lane + 32], r1);
        }
        r0 = fmaxf(r0, 0.0f);
        r1 = fmaxf(r1, 0.0f);

        float p0 = r0 * sW2[lane * 2 + 0] + r1 * sW2[(lane + 32) * 2 + 0];
        float p1 = r0 * sW2[lane * 2 + 1] + r1 * sW2[(lane + 32) * 2 + 1];
        #pragma unroll
        for (int off = 16; off > 0; off >>= 1) {
            p0 += __shfl_xor_sync(0xFFFFFFFFu, p0, off);
            p1 += __shfl_xor_sync(0xFFFFFFFFu, p1, off);
        }
        if (lane == 0) {
            out[row * 2 + 0] = p0 + sB2r[0];
            out[row * 2 + 1] = p1 + sB2r[1];
        }
    }
}

// ---- launch ----------------------------------------------------------------
extern "C" void kernel_launch(void* const* d_in, const int* in_sizes, int n_in,
                              void* d_out, int out_size) {
    const float* neighbors = (const float*)d_in[0];
    const float* phi_w1    = (const float*)d_in[1];
    const float* phi_b1    = (const float*)d_in[2];
    const float* phi_w2    = (const float*)d_in[3];
    const float* phi_b2    = (const float*)d_in[4];
    const float* rho_w1    = (const float*)d_in[5];
    const float* rho_b1    = (const float*)d_in[6];
    const float* rho_w2    = (const float*)d_in[7];
    const float* rho_b2    = (const float*)d_in[8];
    const int*   seg       = (const int*)d_in[9];
    float* out = (float*)d_out;

    const int nNb     = in_sizes[0] / 64;
    const int nAgents = out_size / 2;
    const int nTiles  = (nNb + H_ROWS - 1) / H_ROWS;

    cudaFuncSetAttribute(DeepSet_phi_kernel,
                         cudaFuncAttributeMaxDynamicSharedMemorySize, SMEM_TOTAL);

    DeepSet_zero_kernel<<<512, 256>>>(nAgents * 64);

    int grid = 296;  // 148 SMs x 2 CTAs = 4 streams/SM
    if (grid * 2 > nTiles) grid = (nTiles + 1) / 2;
    DeepSet_phi_kernel<<<grid, 256, SMEM_TOTAL>>>(
        neighbors, phi_w1, phi_b1, phi_w2, phi_b2, seg, nNb, nTiles);

    DeepSet_rho_kernel<<<(nAgents + 63) / 64, 256>>>(rho_w1, rho_b1, rho_w2, rho_b2,
                                                     out, nAgents);
}